// round 3
// baseline (speedup 1.0000x reference)
#include <cuda_runtime.h>
#include <cstdint>

#define HH 1024
#define WW 1024
#define EPSV 1e-6f
#define BGW  1e-4f

// Scratch: per-pixel accumulator (r,g,b,wsum). 16 MB static device array.
__device__ float4 g_accum[HH * WW];

// Camera params in constant memory: Rt(12) + fx,fy,cx,cy. Filled each launch
// by a 64-byte D2D cudaMemcpyToSymbolAsync (graph-capturable memcpy node).
__constant__ float c_cam[16];

// ---------------------------------------------------------------------------
// Kernel 1: project + scatter. 2 points per thread via three LDG.128.
// Point row: [x, y, z, f0, f1, f2]  -> 2 points = 12 floats = 3 float4.
// Strict _rn arithmetic on the path feeding floor() (matches JAX rounding;
// FMA contraction flips floor bins -> 2.6e-3 error, proven in round 1).
// ---------------------------------------------------------------------------
__device__ __forceinline__ void project_and_splat(
    float x, float y, float z, float f0, float f1, float f2) {

    float px = __fadd_rn(__fadd_rn(__fadd_rn(__fmul_rn(c_cam[0], x), __fmul_rn(c_cam[1], y)),
                                   __fmul_rn(c_cam[2], z)), c_cam[3]);
    float py = __fadd_rn(__fadd_rn(__fadd_rn(__fmul_rn(c_cam[4], x), __fmul_rn(c_cam[5], y)),
                                   __fmul_rn(c_cam[6], z)), c_cam[7]);
    float pz = __fadd_rn(__fadd_rn(__fadd_rn(__fmul_rn(c_cam[8], x), __fmul_rn(c_cam[9], y)),
                                   __fmul_rn(c_cam[10], z)), c_cam[11]);

    float inv_z = __fdiv_rn(1.0f, fmaxf(pz, EPSV));
    float u = __fadd_rn(__fmul_rn(__fmul_rn(c_cam[12], px), inv_z), c_cam[14]);
    float v = __fadd_rn(__fmul_rn(__fmul_rn(c_cam[13], py), inv_z), c_cam[15]);

    bool valid = (pz > EPSV) & (u >= 0.0f) & (u < (float)WW)
                            & (v >= 0.0f) & (v < (float)HH);
    if (!valid) return;

    int idx = ((int)floorf(v)) * WW + (int)floorf(u);
    float w = inv_z;
    float4* dst = &g_accum[idx];
    asm volatile("red.global.add.v4.f32 [%0], {%1, %2, %3, %4};"
                 :: "l"(dst),
                    "f"(__fmul_rn(w, f0)),
                    "f"(__fmul_rn(w, f1)),
                    "f"(__fmul_rn(w, f2)),
                    "f"(w)
                 : "memory");
}

__global__ void splat_kernel(const float* __restrict__ pts, int npairs) {
    int t = blockIdx.x * blockDim.x + threadIdx.x;
    if (t >= npairs) return;

    const float4* p = reinterpret_cast<const float4*>(pts + 12ll * t);
    float4 q0 = __ldg(p + 0);   // x0 y0 z0 f00
    float4 q1 = __ldg(p + 1);   // f01 f02 x1 y1
    float4 q2 = __ldg(p + 2);   // z1 f10 f11 f12

    project_and_splat(q0.x, q0.y, q0.z, q0.w, q1.x, q1.y);
    project_and_splat(q1.z, q1.w, q2.x, q2.y, q2.z, q2.w);
}

// ---------------------------------------------------------------------------
// Kernel 2: normalize, 4 pixels/thread, float4 env/out I/O.
// Fast reciprocal instead of 12 IEEE divisions (error ~2e-7, far under 1e-3).
// ---------------------------------------------------------------------------
__global__ void normalize_kernel(const float* __restrict__ env,
                                 float* __restrict__ out) {
    int t = blockIdx.x * blockDim.x + threadIdx.x;   // pixel-group id
    int base_pix = t * 4;
    if (base_pix >= HH * WW) return;

    const float4* e4 = reinterpret_cast<const float4*>(env + 12ll * t);
    float4 e0 = __ldg(e4 + 0);
    float4 e1 = __ldg(e4 + 1);
    float4 e2 = __ldg(e4 + 2);

    float ev[12] = { e0.x, e0.y, e0.z, e0.w,
                     e1.x, e1.y, e1.z, e1.w,
                     e2.x, e2.y, e2.z, e2.w };
    float ov[12];

    #pragma unroll
    for (int k = 0; k < 4; k++) {
        float4 acc = g_accum[base_pix + k];
        float inv = __fdividef(1.0f, __fadd_rn(acc.w, BGW));
        ov[3 * k + 0] = __fmul_rn(__fadd_rn(acc.x, __fmul_rn(BGW, ev[3 * k + 0])), inv);
        ov[3 * k + 1] = __fmul_rn(__fadd_rn(acc.y, __fmul_rn(BGW, ev[3 * k + 1])), inv);
        ov[3 * k + 2] = __fmul_rn(__fadd_rn(acc.z, __fmul_rn(BGW, ev[3 * k + 2])), inv);
    }

    float4* o4 = reinterpret_cast<float4*>(out + 12ll * t);
    o4[0] = make_float4(ov[0], ov[1], ov[2],  ov[3]);
    o4[1] = make_float4(ov[4], ov[5], ov[6],  ov[7]);
    o4[2] = make_float4(ov[8], ov[9], ov[10], ov[11]);
}

// ---------------------------------------------------------------------------
// Launch: copy camera->constant, memset accum -> splat -> normalize.
// Inputs: 0=cam_type(int,1), 1=camera(16 f32), 2=points(N*6 f32),
//         3=environment(H*W*3 f32)
// ---------------------------------------------------------------------------
extern "C" void kernel_launch(void* const* d_in, const int* in_sizes, int n_in,
                              void* d_out, int out_size) {
    const float* camera = (const float*)d_in[1];
    const float* points = (const float*)d_in[2];
    const float* env    = (const float*)d_in[3];
    float* out          = (float*)d_out;

    int n = in_sizes[2] / 6;
    int npairs = n / 2;   // N = 4,000,000 -> even; guarded below anyway

    cudaMemcpyToSymbolAsync(c_cam, camera, 16 * sizeof(float), 0,
                            cudaMemcpyDeviceToDevice, 0);

    void* accum_addr = nullptr;
    cudaGetSymbolAddress(&accum_addr, g_accum);
    cudaMemsetAsync(accum_addr, 0, sizeof(float4) * HH * WW, 0);

    {
        int threads = 256;
        int blocks = (npairs + threads - 1) / threads;
        splat_kernel<<<blocks, threads>>>(points, npairs);
    }
    {
        int groups = (HH * WW) / 4;
        int threads = 256;
        int blocks = (groups + threads - 1) / threads;
        normalize_kernel<<<blocks, threads>>>(env, out);
    }
}

// round 4
// speedup vs baseline: 1.0007x; 1.0007x over previous
#include <cuda_runtime.h>
#include <cstdint>

#define HH 1024
#define WW 1024
#define EPSV 1e-6f
#define BGW  1e-4f

// Scratch: per-pixel accumulator (r,g,b,wsum). 16 MB static device array.
// Zero-initialized at module load; normalize_kernel re-zeros it after reading,
// so every kernel_launch call (and every graph replay) sees zeros. No memset.
__device__ float4 g_accum[HH * WW];

// ---------------------------------------------------------------------------
// Kernel 1: project + scatter. 2 points per thread via three LDG.128.
// Point row: [x, y, z, f0, f1, f2]  -> 2 points = 12 floats = 3 float4.
// Strict _rn arithmetic on the path feeding floor() (matches JAX rounding;
// FMA contraction flips floor bins -> 2.6e-3 error, proven in round 1).
// Camera read via __ldg broadcast (L1-cached; ptxas hoists — proven cheap in
// round 2; the constant-memory + memcpy-node variant cost ~3us of graph
// overhead in round 3).
// ---------------------------------------------------------------------------
__device__ __forceinline__ void project_and_splat(
    const float* __restrict__ cam,
    float x, float y, float z, float f0, float f1, float f2) {

    float r00 = __ldg(cam + 0),  r01 = __ldg(cam + 1),  r02 = __ldg(cam + 2),  t0 = __ldg(cam + 3);
    float r10 = __ldg(cam + 4),  r11 = __ldg(cam + 5),  r12 = __ldg(cam + 6),  t1 = __ldg(cam + 7);
    float r20 = __ldg(cam + 8),  r21 = __ldg(cam + 9),  r22 = __ldg(cam + 10), t2 = __ldg(cam + 11);
    float fx  = __ldg(cam + 12), fy  = __ldg(cam + 13), cx = __ldg(cam + 14),  cy = __ldg(cam + 15);

    float px = __fadd_rn(__fadd_rn(__fadd_rn(__fmul_rn(r00, x), __fmul_rn(r01, y)),
                                   __fmul_rn(r02, z)), t0);
    float py = __fadd_rn(__fadd_rn(__fadd_rn(__fmul_rn(r10, x), __fmul_rn(r11, y)),
                                   __fmul_rn(r12, z)), t1);
    float pz = __fadd_rn(__fadd_rn(__fadd_rn(__fmul_rn(r20, x), __fmul_rn(r21, y)),
                                   __fmul_rn(r22, z)), t2);

    float inv_z = __fdiv_rn(1.0f, fmaxf(pz, EPSV));
    float u = __fadd_rn(__fmul_rn(__fmul_rn(fx, px), inv_z), cx);
    float v = __fadd_rn(__fmul_rn(__fmul_rn(fy, py), inv_z), cy);

    bool valid = (pz > EPSV) & (u >= 0.0f) & (u < (float)WW)
                            & (v >= 0.0f) & (v < (float)HH);
    if (!valid) return;

    int idx = ((int)floorf(v)) * WW + (int)floorf(u);
    float w = inv_z;
    float4* dst = &g_accum[idx];
    asm volatile("red.global.add.v4.f32 [%0], {%1, %2, %3, %4};"
                 :: "l"(dst),
                    "f"(__fmul_rn(w, f0)),
                    "f"(__fmul_rn(w, f1)),
                    "f"(__fmul_rn(w, f2)),
                    "f"(w)
                 : "memory");
}

__global__ void splat_kernel(const float* __restrict__ pts,
                             const float* __restrict__ cam,
                             int npairs) {
    int t = blockIdx.x * blockDim.x + threadIdx.x;
    if (t >= npairs) return;

    const float4* p = reinterpret_cast<const float4*>(pts + 12ll * t);
    float4 q0 = __ldg(p + 0);   // x0 y0 z0 f00
    float4 q1 = __ldg(p + 1);   // f01 f02 x1 y1
    float4 q2 = __ldg(p + 2);   // z1 f10 f11 f12

    project_and_splat(cam, q0.x, q0.y, q0.z, q0.w, q1.x, q1.y);
    project_and_splat(cam, q1.z, q1.w, q2.x, q2.y, q2.z, q2.w);
}

// ---------------------------------------------------------------------------
// Kernel 2: normalize, 4 pixels/thread, float4 env/out I/O. Fast reciprocal.
// After reading each accumulator entry, reset it to zero so the next call of
// kernel_launch (graph replay) starts from a clean accumulator.
// ---------------------------------------------------------------------------
__global__ void normalize_kernel(const float* __restrict__ env,
                                 float* __restrict__ out) {
    int t = blockIdx.x * blockDim.x + threadIdx.x;   // pixel-group id
    int base_pix = t * 4;
    if (base_pix >= HH * WW) return;

    const float4* e4 = reinterpret_cast<const float4*>(env + 12ll * t);
    float4 e0 = __ldg(e4 + 0);
    float4 e1 = __ldg(e4 + 1);
    float4 e2 = __ldg(e4 + 2);

    float4 acc0 = g_accum[base_pix + 0];
    float4 acc1 = g_accum[base_pix + 1];
    float4 acc2 = g_accum[base_pix + 2];
    float4 acc3 = g_accum[base_pix + 3];

    // reset for next call (stays in L2; deterministic across graph replays)
    float4 zero = make_float4(0.f, 0.f, 0.f, 0.f);
    g_accum[base_pix + 0] = zero;
    g_accum[base_pix + 1] = zero;
    g_accum[base_pix + 2] = zero;
    g_accum[base_pix + 3] = zero;

    float ev[12] = { e0.x, e0.y, e0.z, e0.w,
                     e1.x, e1.y, e1.z, e1.w,
                     e2.x, e2.y, e2.z, e2.w };
    float4 accs[4] = { acc0, acc1, acc2, acc3 };
    float ov[12];

    #pragma unroll
    for (int k = 0; k < 4; k++) {
        float4 acc = accs[k];
        float inv = __fdividef(1.0f, __fadd_rn(acc.w, BGW));
        ov[3 * k + 0] = __fmul_rn(__fadd_rn(acc.x, __fmul_rn(BGW, ev[3 * k + 0])), inv);
        ov[3 * k + 1] = __fmul_rn(__fadd_rn(acc.y, __fmul_rn(BGW, ev[3 * k + 1])), inv);
        ov[3 * k + 2] = __fmul_rn(__fadd_rn(acc.z, __fmul_rn(BGW, ev[3 * k + 2])), inv);
    }

    float4* o4 = reinterpret_cast<float4*>(out + 12ll * t);
    o4[0] = make_float4(ov[0], ov[1], ov[2],  ov[3]);
    o4[1] = make_float4(ov[4], ov[5], ov[6],  ov[7]);
    o4[2] = make_float4(ov[8], ov[9], ov[10], ov[11]);
}

// ---------------------------------------------------------------------------
// Launch: splat -> normalize (normalize also re-zeros the accumulator).
// Inputs: 0=cam_type(int,1), 1=camera(16 f32), 2=points(N*6 f32),
//         3=environment(H*W*3 f32)
// ---------------------------------------------------------------------------
extern "C" void kernel_launch(void* const* d_in, const int* in_sizes, int n_in,
                              void* d_out, int out_size) {
    const float* camera = (const float*)d_in[1];
    const float* points = (const float*)d_in[2];
    const float* env    = (const float*)d_in[3];
    float* out          = (float*)d_out;

    int n = in_sizes[2] / 6;
    int npairs = n / 2;

    {
        int threads = 256;
        int blocks = (npairs + threads - 1) / threads;
        splat_kernel<<<blocks, threads>>>(points, camera, npairs);
    }
    {
        int groups = (HH * WW) / 4;
        int threads = 256;
        int blocks = (groups + threads - 1) / threads;
        normalize_kernel<<<blocks, threads>>>(env, out);
    }
}